// round 1
// baseline (speedup 1.0000x reference)
#include <cuda_runtime.h>

#define B_   16
#define T_   256
#define NTR_ 1024
#define NTE_ 256
#define NALL 1280

#define L2E      1.4426950408889634f
#define LOG2_L2E 0.5287663729448977f

// Per-n constants: [P, Q, AL, w0, rfx', rfy', w1, pad]
__device__ float d_nc[NALL * 8];
// Per-(b,t): [sin z0, cos z0]
__device__ float d_btc[B_ * T_ * 2];
// Bicubic coefficient table C[j*4+i]
__device__ float d_C[16];
// Global scalars: kx, ky, ax, ay
__device__ float d_g[4];

__device__ __forceinline__ float ex2(float x) {
    float r;
    asm("ex2.approx.f32 %0, %1;" : "=f"(r) : "f"(x));
    return r;
}

__global__ void setup_kernel(const float* __restrict__ z0,
                             const float* __restrict__ coeff0,
                             const float* __restrict__ mean0,
                             const float* __restrict__ log_var0,
                             const float* __restrict__ coeff1,
                             const float* __restrict__ mean1,
                             const float* __restrict__ log_var1,
                             const float* __restrict__ rf_tr0,
                             const float* __restrict__ rf_tr1,
                             const float* __restrict__ rf_te0,
                             const float* __restrict__ rf_te1,
                             const float* __restrict__ ew_tr,
                             const float* __restrict__ ew_te,
                             const float* __restrict__ lfs_tr,
                             const float* __restrict__ lfs_te)
{
    int idx = blockIdx.x * blockDim.x + threadIdx.x;

    if (idx < NALL) {
        int nn;
        const float *rf0, *rf1, *ew, *lfs;
        if (idx < NTR_) { nn = idx;        rf0 = rf_tr0; rf1 = rf_tr1; ew = ew_tr; lfs = lfs_tr; }
        else            { nn = idx - NTR_; rf0 = rf_te0; rf1 = rf_te1; ew = ew_te; lfs = lfs_te; }

        // Torus ensemble (K0=1, L0=1):
        // resp0 = coeff0 * exp(-(1 - 2*(s*ms + c*mc) + |m|^2)/v0^2)
        float mu  = mean0[0];
        float ms  = sinf(mu) - sinf(rf0[nn]);
        float mc  = cosf(mu) - cosf(rf0[nn]);
        float v0  = expf(log_var0[0]);
        float iv0 = 1.0f / (v0 * v0);
        float A   = coeff0[0] * expf(-(1.0f + ms * ms + mc * mc) * iv0);
        float P   = 2.0f * ms * iv0 * L2E;
        float Q   = 2.0f * mc * iv0 * L2E;

        // softmax(ew) * exp(lfs)
        float e0w = ew[nn * 2], e1w = ew[nn * 2 + 1];
        float mx  = fmaxf(e0w, e1w);
        float ea  = expf(e0w - mx), eb = expf(e1w - mx);
        float scl = expf(lfs[nn]) / (ea + eb);

        float gx0 = mean1[0], gy0 = mean1[1];

        d_nc[idx * 8 + 0] = P;
        d_nc[idx * 8 + 1] = Q;
        d_nc[idx * 8 + 2] = A * L2E;          // AL: e0 = exp2(AL * t0)
        d_nc[idx * 8 + 3] = ea * scl;         // w0
        d_nc[idx * 8 + 4] = rf1[nn * 2 + 0] - gx0;
        d_nc[idx * 8 + 5] = rf1[nn * 2 + 1] - gy0;
        d_nc[idx * 8 + 6] = eb * scl;         // w1
        d_nc[idx * 8 + 7] = 0.0f;
    } else if (idx < NALL + 16) {
        // Bicubic table: C[j*4+i] = coeff1[i*4+j] * exp(-i^2 dx^2/vx^2 - j^2 dy^2/vy^2)
        int e = idx - NALL;
        int i = e & 3, j = e >> 2;
        float dx  = mean1[8] - mean1[0];      // k=4 -> (i=1,j=0), dim 0
        float dy  = mean1[3] - mean1[1];      // k=1 -> (i=0,j=1), dim 1
        float vx  = expf(log_var1[0]);
        float vy  = expf(log_var1[1]);
        float ivx = 1.0f / (vx * vx), ivy = 1.0f / (vy * vy);
        d_C[e] = coeff1[i * 4 + j] *
                 expf(-(float)(i * i) * dx * dx * ivx - (float)(j * j) * dy * dy * ivy);
    } else if (idx == NALL + 16) {
        float dx  = mean1[8] - mean1[0];
        float dy  = mean1[3] - mean1[1];
        float vx  = expf(log_var1[0]);
        float vy  = expf(log_var1[1]);
        float ivx = 1.0f / (vx * vx), ivy = 1.0f / (vy * vy);
        d_g[0] = 2.0f * dx * ivx * L2E;       // kx
        d_g[1] = 2.0f * dy * ivy * L2E;       // ky
        d_g[2] = ivx * L2E;                   // ax
        d_g[3] = ivy * L2E;                   // ay
    } else if (idx >= 1536 && idx < 1536 + B_ * T_) {
        int m = idx - 1536;
        float z = z0[m];
        d_btc[m * 2 + 0] = sinf(z);
        d_btc[m * 2 + 1] = cosf(z);
    }
}

// One block = (b, group of 4 n), 256 threads over t. 4 outputs per thread.
__global__ void __launch_bounds__(256)
decoder_main(const float* __restrict__ z1, float* __restrict__ out)
{
    int bid = blockIdx.x;
    int b   = bid / (NALL / 4);
    int ng  = bid % (NALL / 4);
    int t   = threadIdx.x;
    int bt  = b * T_ + t;

    float2 sc = ((const float2*)d_btc)[bt];
    float2 zv = ((const float2*)z1)[bt];

    float C[16];
#pragma unroll
    for (int q = 0; q < 16; q++) C[q] = d_C[q];
    float kx = d_g[0], ky = d_g[1], ax = d_g[2], ay = d_g[3];

#pragma unroll
    for (int q = 0; q < 4; q++) {
        int n = ng * 4 + q;
        float4 na = ((const float4*)d_nc)[n * 2];
        float4 nb = ((const float4*)d_nc)[n * 2 + 1];

        // Torus: e0 = exp(resp0) = exp2(AL * exp2(P*s + Q*c))
        float t0 = ex2(fmaf(sc.x, na.x, sc.y * na.y));
        float e0 = ex2(na.z * t0);

        // Euclidean (separable bicubic in tx, ty)
        float ux = zv.x + nb.x, uy = zv.y + nb.y;
        float tx = ex2(kx * ux);
        float ty = ex2(ky * uy);
        float la = fmaf(-ax * ux, ux, fmaf(-ay * uy, uy, LOG2_L2E));
        float lead = ex2(la);   // = L2E * exp(-ux^2/vx^2 - uy^2/vy^2)

        float tx2 = tx * tx, tx3 = tx2 * tx;
        float ty2 = ty * ty, ty3 = ty2 * ty;
        float S0 = fmaf(C[3],  tx3, fmaf(C[2],  tx2, fmaf(C[1],  tx, C[0])));
        float S1 = fmaf(C[7],  tx3, fmaf(C[6],  tx2, fmaf(C[5],  tx, C[4])));
        float S2 = fmaf(C[11], tx3, fmaf(C[10], tx2, fmaf(C[9],  tx, C[8])));
        float S3 = fmaf(C[15], tx3, fmaf(C[14], tx2, fmaf(C[13], tx, C[12])));
        float S  = fmaf(S3, ty3, fmaf(S2, ty2, fmaf(S1, ty, S0)));
        float e1 = ex2(lead * S);   // exp(resp1)

        float val = fmaf(na.w, e0, nb.z * e1);

        int off;
        if (n < NTR_) off = (b * NTR_ + n) * T_ + t;
        else          off = B_ * NTR_ * T_ + (b * NTE_ + (n - NTR_)) * T_ + t;
        out[off] = val;
    }
}

extern "C" void kernel_launch(void* const* d_in, const int* in_sizes, int n_in,
                              void* d_out, int out_size)
{
    const float* z0       = (const float*)d_in[0];
    const float* z1       = (const float*)d_in[1];
    const float* coeff0   = (const float*)d_in[2];
    const float* mean0    = (const float*)d_in[3];
    const float* log_var0 = (const float*)d_in[4];
    const float* coeff1   = (const float*)d_in[5];
    const float* mean1    = (const float*)d_in[6];
    const float* log_var1 = (const float*)d_in[7];
    const float* rf_tr0   = (const float*)d_in[8];
    const float* rf_tr1   = (const float*)d_in[9];
    const float* rf_te0   = (const float*)d_in[10];
    const float* rf_te1   = (const float*)d_in[11];
    const float* ew_tr    = (const float*)d_in[12];
    const float* ew_te    = (const float*)d_in[13];
    const float* lfs_tr   = (const float*)d_in[14];
    const float* lfs_te   = (const float*)d_in[15];

    setup_kernel<<<22, 256>>>(z0, coeff0, mean0, log_var0, coeff1, mean1, log_var1,
                              rf_tr0, rf_tr1, rf_te0, rf_te1,
                              ew_tr, ew_te, lfs_tr, lfs_te);
    decoder_main<<<B_ * (NALL / 4), 256>>>(z1, (float*)d_out);
}

// round 2
// speedup vs baseline: 1.2145x; 1.2145x over previous
#include <cuda_runtime.h>

#define B_   16
#define T_   256
#define NTR_ 1024
#define NTE_ 256
#define NALL 1280
#define NG   8            // n's per block
#define NP   4            // packed pairs per block

#define L2E      1.4426950408889634f
#define LOG2_L2E 0.5287663729448977f

typedef unsigned long long u64;

__device__ __forceinline__ float ex2(float x) {
    float r;
    asm("ex2.approx.f32 %0, %1;" : "=f"(r) : "f"(x));
    return r;
}
__device__ __forceinline__ u64 pk(float lo, float hi) {
    u64 r; asm("mov.b64 %0, {%1,%2};" : "=l"(r) : "f"(lo), "f"(hi)); return r;
}
__device__ __forceinline__ void upk(u64 v, float& lo, float& hi) {
    asm("mov.b64 {%0,%1}, %2;" : "=f"(lo), "=f"(hi) : "l"(v));
}
__device__ __forceinline__ u64 f2fma(u64 a, u64 b, u64 c) {
    u64 d; asm("fma.rn.f32x2 %0, %1, %2, %3;" : "=l"(d) : "l"(a), "l"(b), "l"(c)); return d;
}
__device__ __forceinline__ u64 f2mul(u64 a, u64 b) {
    u64 d; asm("mul.rn.f32x2 %0, %1, %2;" : "=l"(d) : "l"(a), "l"(b)); return d;
}
__device__ __forceinline__ u64 f2add(u64 a, u64 b) {
    u64 d; asm("add.rn.f32x2 %0, %1, %2;" : "=l"(d) : "l"(a), "l"(b)); return d;
}

// One block = (b, group of 8 n). 256 threads over t. 8 outputs per thread,
// processed as 4 packed f32x2 pairs.
__global__ void __launch_bounds__(256)
decoder_fused(const float* __restrict__ z0,
              const float* __restrict__ z1,
              const float* __restrict__ coeff0,
              const float* __restrict__ mean0,
              const float* __restrict__ log_var0,
              const float* __restrict__ coeff1,
              const float* __restrict__ mean1,
              const float* __restrict__ log_var1,
              const float* __restrict__ rf_tr0,
              const float* __restrict__ rf_tr1,
              const float* __restrict__ rf_te0,
              const float* __restrict__ rf_te1,
              const float* __restrict__ ew_tr,
              const float* __restrict__ ew_te,
              const float* __restrict__ lfs_tr,
              const float* __restrict__ lfs_te,
              float* __restrict__ out)
{
    __shared__ u64 sP[NP], sQ[NP], sAL[NP], sW0[NP], sW1[NP];
    __shared__ u64 sRx[NP], sRy[NP], sPx[NP], sPy[NP], sLn[NP];
    __shared__ u64 sC[16];           // broadcast-packed bicubic coeffs
    __shared__ float sG[4];          // kxl, kyl, axl, ayl

    const int tid = threadIdx.x;
    const int bid = blockIdx.x;
    const int b   = bid / (NALL / NG);
    const int ng  = bid % (NALL / NG);
    const int n0  = ng * NG;

    // ---- in-block constant prep ----
    if (tid < NG) {
        int n = n0 + tid;
        int nn; const float *rf0, *rf1, *ew, *lfs;
        if (n < NTR_) { nn = n;        rf0 = rf_tr0; rf1 = rf_tr1; ew = ew_tr; lfs = lfs_tr; }
        else          { nn = n - NTR_; rf0 = rf_te0; rf1 = rf_te1; ew = ew_te; lfs = lfs_te; }

        // Torus (K0=1, L0=1): resp0 = A*exp(2(s*ms+c*mc)/v0^2); e0 = exp(resp0)
        float mu  = mean0[0];
        float ms  = sinf(mu) - sinf(rf0[nn]);
        float mc  = cosf(mu) - cosf(rf0[nn]);
        float v0  = expf(log_var0[0]);
        float iv0 = 1.0f / (v0 * v0);
        float A   = coeff0[0] * expf(-(1.0f + ms * ms + mc * mc) * iv0);
        ((float*)sP)[tid]  = 2.0f * ms * iv0 * L2E;
        ((float*)sQ)[tid]  = 2.0f * mc * iv0 * L2E;
        ((float*)sAL)[tid] = A * L2E;

        // softmax(ew) * exp(lfs)
        float e0w = ew[nn * 2], e1w = ew[nn * 2 + 1];
        float mx  = fmaxf(e0w, e1w);
        float ea  = expf(e0w - mx), eb = expf(e1w - mx);
        float scl = expf(lfs[nn]) / (ea + eb);
        ((float*)sW0)[tid] = ea * scl;
        ((float*)sW1)[tid] = eb * scl;

        // Euclidean per-n factors
        float dx  = mean1[8] - mean1[0];
        float dy  = mean1[3] - mean1[1];
        float vx  = expf(log_var1[0]), vy = expf(log_var1[1]);
        float ivx = 1.0f / (vx * vx),  ivy = 1.0f / (vy * vy);
        float axl = ivx * L2E,         ayl = ivy * L2E;
        float kxl = 2.0f * dx * ivx * L2E, kyl = 2.0f * dy * ivy * L2E;
        float rx  = rf1[nn * 2 + 0] - mean1[0];
        float ry  = rf1[nn * 2 + 1] - mean1[1];
        ((float*)sRx)[tid] = exp2f(kxl * rx);
        ((float*)sRy)[tid] = exp2f(kyl * ry);
        ((float*)sPx)[tid] = -2.0f * axl * rx;
        ((float*)sPy)[tid] = -2.0f * ayl * ry;
        ((float*)sLn)[tid] = -axl * rx * rx - ayl * ry * ry;
    } else if (tid >= 32 && tid < 48) {
        // Bicubic table: C[j*4+i] = coeff1[i*4+j] * exp(-i^2 dx^2 ivx - j^2 dy^2 ivy)
        int e = tid - 32;
        int i = e & 3, j = e >> 2;
        float dx  = mean1[8] - mean1[0];
        float dy  = mean1[3] - mean1[1];
        float vx  = expf(log_var1[0]), vy = expf(log_var1[1]);
        float ivx = 1.0f / (vx * vx),  ivy = 1.0f / (vy * vy);
        float v = coeff1[i * 4 + j] *
                  expf(-(float)(i * i) * dx * dx * ivx - (float)(j * j) * dy * dy * ivy);
        ((float*)&sC[e])[0] = v;
        ((float*)&sC[e])[1] = v;
    } else if (tid == 64) {
        float dx  = mean1[8] - mean1[0];
        float dy  = mean1[3] - mean1[1];
        float vx  = expf(log_var1[0]), vy = expf(log_var1[1]);
        float ivx = 1.0f / (vx * vx),  ivy = 1.0f / (vy * vy);
        sG[0] = 2.0f * dx * ivx * L2E;   // kxl
        sG[1] = 2.0f * dy * ivy * L2E;   // kyl
        sG[2] = ivx * L2E;               // axl
        sG[3] = ivy * L2E;               // ayl
    }
    __syncthreads();

    // ---- per-thread (b,t) terms ----
    const int t  = tid;
    const int bt = b * T_ + t;

    float kxl = sG[0], kyl = sG[1], axl = sG[2], ayl = sG[3];

    float zz = z0[bt];
    float s  = __sinf(zz);
    float c  = __cosf(zz);
    float2 zv = ((const float2*)z1)[bt];

    float Tx = ex2(kxl * zv.x);
    float Ty = ex2(kyl * zv.y);
    float Lt = fmaf(-axl * zv.x, zv.x, fmaf(-ayl * zv.y, zv.y, LOG2_L2E));

    u64 ssp = pk(s, s),       ccp = pk(c, c);
    u64 Txp = pk(Tx, Tx),     Typ = pk(Ty, Ty);
    u64 zxp = pk(zv.x, zv.x), zyp = pk(zv.y, zv.y);
    u64 Ltp = pk(Lt, Lt);

    u64 C0 = sC[0],  C1 = sC[1],  C2 = sC[2],  C3 = sC[3];
    u64 C4 = sC[4],  C5 = sC[5],  C6 = sC[6],  C7 = sC[7];
    u64 C8 = sC[8],  C9 = sC[9],  C10 = sC[10], C11 = sC[11];
    u64 C12 = sC[12], C13 = sC[13], C14 = sC[14], C15 = sC[15];

    int base;
    if (n0 < NTR_) base = (b * NTR_ + n0) * T_ + t;
    else           base = B_ * NTR_ * T_ + (b * NTE_ + (n0 - NTR_)) * T_ + t;
    float* op = out + base;

#pragma unroll
    for (int p = 0; p < NP; p++) {
        float a0, a1;

        // Torus: e0 = exp2(AL * exp2(P*s + Q*c))
        u64 targ = f2fma(sP[p], ssp, f2mul(sQ[p], ccp));
        upk(targ, a0, a1);
        u64 t0p = pk(ex2(a0), ex2(a1));
        u64 e0a = f2mul(sAL[p], t0p);
        upk(e0a, a0, a1);
        u64 e0p = pk(ex2(a0), ex2(a1));

        // Euclidean: tx/ty via per-n factors, lead via split exponent
        u64 txp = f2mul(sRx[p], Txp);
        u64 typ = f2mul(sRy[p], Typ);
        u64 lap = f2fma(sPx[p], zxp, f2fma(sPy[p], zyp, f2add(sLn[p], Ltp)));
        upk(lap, a0, a1);
        u64 leadp = pk(ex2(a0), ex2(a1));

        // bicubic Horner in tx (rows), then ty
        u64 r0 = f2fma(f2fma(f2fma(C3,  txp, C2),  txp, C1),  txp, C0);
        u64 r1 = f2fma(f2fma(f2fma(C7,  txp, C6),  txp, C5),  txp, C4);
        u64 r2 = f2fma(f2fma(f2fma(C11, txp, C10), txp, C9),  txp, C8);
        u64 r3 = f2fma(f2fma(f2fma(C15, txp, C14), txp, C13), txp, C12);
        u64 S  = f2fma(f2fma(f2fma(r3, typ, r2), typ, r1), typ, r0);

        u64 e1a = f2mul(leadp, S);
        upk(e1a, a0, a1);
        u64 e1p = pk(ex2(a0), ex2(a1));

        u64 valp = f2fma(sW0[p], e0p, f2mul(sW1[p], e1p));
        float v0, v1;
        upk(valp, v0, v1);
        op[(2 * p)     * T_] = v0;
        op[(2 * p + 1) * T_] = v1;
    }
}

extern "C" void kernel_launch(void* const* d_in, const int* in_sizes, int n_in,
                              void* d_out, int out_size)
{
    const float* z0       = (const float*)d_in[0];
    const float* z1       = (const float*)d_in[1];
    const float* coeff0   = (const float*)d_in[2];
    const float* mean0    = (const float*)d_in[3];
    const float* log_var0 = (const float*)d_in[4];
    const float* coeff1   = (const float*)d_in[5];
    const float* mean1    = (const float*)d_in[6];
    const float* log_var1 = (const float*)d_in[7];
    const float* rf_tr0   = (const float*)d_in[8];
    const float* rf_tr1   = (const float*)d_in[9];
    const float* rf_te0   = (const float*)d_in[10];
    const float* rf_te1   = (const float*)d_in[11];
    const float* ew_tr    = (const float*)d_in[12];
    const float* ew_te    = (const float*)d_in[13];
    const float* lfs_tr   = (const float*)d_in[14];
    const float* lfs_te   = (const float*)d_in[15];

    decoder_fused<<<B_ * (NALL / NG), 256>>>(
        z0, z1, coeff0, mean0, log_var0, coeff1, mean1, log_var1,
        rf_tr0, rf_tr1, rf_te0, rf_te1, ew_tr, ew_te, lfs_tr, lfs_te,
        (float*)d_out);
}